// round 8
// baseline (speedup 1.0000x reference)
#include <cuda_runtime.h>
#include <cuda_bf16.h>
#include <math.h>
#include <stdint.h>

// ---------------- problem constants ----------------
#define T_TOK 4096
#define H_DIM 1024
#define F_DIM 2816
#define E_NUM 8
#define NROWS (T_TOK*2)
#define BM 128
#define RCAP (NROWS + E_NUM*BM)   // 9216
#define N1 (2*F_DIM)              // 5632
#define NBLK_ROUTER 32
// tf32 stage: A(128 rows x 144B) | B(128 rows x 144B)
#define SUBA 18432
#define STAGE (2*SUBA)            // 36864
#define SMEM_DYN (2*STAGE)        // 73728
#define NK1 32                    // 1024/32
#define NK2 88                    // 2816/32
#define MAXTILES 72
// prep partition
#define NB_T1 22528
#define NB_T2 22528
#define NB_CX 4096
#define NB_IN 36

// ---------------- device scratch ----------------
__device__ int   g_eidx[NROWS];
__device__ float g_wgt[NROWS];
__device__ int   g_cnt[E_NUM];
__device__ int   g_pos[NROWS];
__device__ int   g_list[RCAP];
__device__ float g_partsP[NBLK_ROUTER][E_NUM];

__device__ __align__(16) float g_x [(size_t)T_TOK*H_DIM];        // tf32-rounded x
__device__ __align__(16) float g_b1[(size_t)E_NUM*N1*H_DIM];     // [e][n(gate|up)][h] tf32
__device__ __align__(16) float g_b2[(size_t)E_NUM*H_DIM*F_DIM];  // [e][n(h)][f] tf32
__device__ __align__(16) float g_h [(size_t)RCAP*F_DIM];         // silu(g)*u, tf32-rounded
__device__ __align__(16) float g_y [(size_t)NROWS*H_DIM];

// ---------------- PTX helpers ----------------
__device__ __forceinline__ uint32_t s2u(const void* p){
    uint32_t a;
    asm("{ .reg .u64 t; cvta.to.shared.u64 t, %1; cvt.u32.u64 %0, t; }" : "=r"(a) : "l"(p));
    return a;
}
__device__ __forceinline__ void cp16(uint32_t dst, const void* src, int n){
    asm volatile("cp.async.cg.shared.global [%0], [%1], 16, %2;" :: "r"(dst), "l"(src), "r"(n) : "memory");
}
__device__ __forceinline__ void cp_commit(){ asm volatile("cp.async.commit_group;" ::: "memory"); }
__device__ __forceinline__ uint32_t lds32(uint32_t a){
    uint32_t v; asm volatile("ld.shared.b32 %0, [%1];" : "=r"(v) : "r"(a)); return v;
}
__device__ __forceinline__ void mmaT(float* c, const uint32_t* a, uint32_t b0, uint32_t b1){
    asm volatile("mma.sync.aligned.m16n8k8.row.col.f32.tf32.tf32.f32 "
                 "{%0,%1,%2,%3},{%4,%5,%6,%7},{%8,%9},{%0,%1,%2,%3};"
        : "+f"(c[0]),"+f"(c[1]),"+f"(c[2]),"+f"(c[3])
        : "r"(a[0]),"r"(a[1]),"r"(a[2]),"r"(a[3]), "r"(b0),"r"(b1));
}
__device__ __forceinline__ float rna(float v){
    uint32_t r; asm("cvt.rna.tf32.f32 %0, %1;" : "=r"(r) : "f"(v));
    return __uint_as_float(r);
}
__device__ __forceinline__ int tile_scan(int tile, int& e_out, int& m0_out, int& base_out){
    int acc = 0, base = 0;
#pragma unroll
    for (int q = 0; q < E_NUM; q++){
        int c = __ldg(&g_cnt[q]);
        int nt = (c + 127) >> 7;
        if (tile < acc + nt){
            e_out = q; m0_out = (tile - acc) << 7; base_out = base;
            return 1;
        }
        acc += nt;
        base += nt << 7;
    }
    return 0;
}

// ---------------- prep: t1 + t2 + convx + init ----------------
__global__ void prep_kernel(const float* __restrict__ x,
                            const float* __restrict__ wg,
                            const float* __restrict__ wu,
                            const float* __restrict__ wd){
    __shared__ float sg[32][33], su[32][33];
    int b = blockIdx.x;
    int tid = threadIdx.x;
    int tx = tid & 31, ty = tid >> 5;

    if (b < NB_T1){
        int e = b / 2816, rem = b % 2816;
        int h0 = (rem / 88) * 32, f0 = (rem % 88) * 32;
        const float* pg = wg + ((size_t)e*H_DIM + h0)*F_DIM + f0;
        const float* pu = wu + ((size_t)e*H_DIM + h0)*F_DIM + f0;
#pragma unroll
        for (int j = 0; j < 4; j++){
            int hl = ty + j*8;
            sg[hl][tx] = pg[(size_t)hl*F_DIM + tx];
            su[hl][tx] = pu[(size_t)hl*F_DIM + tx];
        }
        __syncthreads();
#pragma unroll
        for (int j = 0; j < 4; j++){
            int fl = ty + j*8;
            g_b1[((size_t)e*N1 + f0 + fl)*H_DIM + h0 + tx]         = rna(sg[tx][fl]);
            g_b1[((size_t)e*N1 + F_DIM + f0 + fl)*H_DIM + h0 + tx] = rna(su[tx][fl]);
        }
    } else if (b < NB_T1 + NB_T2){
        int bb = b - NB_T1;
        int e = bb / 2816, rem = bb % 2816;
        int h0 = (rem / 88) * 32, f0 = (rem % 88) * 32;
        const float* pd = wd + ((size_t)e*F_DIM + f0)*H_DIM + h0;
#pragma unroll
        for (int j = 0; j < 4; j++){
            int fl = ty + j*8;
            sg[fl][tx] = pd[(size_t)fl*H_DIM + tx];
        }
        __syncthreads();
#pragma unroll
        for (int j = 0; j < 4; j++){
            int hl = ty + j*8;
            g_b2[((size_t)e*H_DIM + h0 + hl)*F_DIM + f0 + tx] = rna(sg[tx][hl]);
        }
    } else if (b < NB_T1 + NB_T2 + NB_CX){
        int i = (b - NB_T1 - NB_T2)*256 + tid;
        float4 v = ((const float4*)x)[i];
        float4 o = make_float4(rna(v.x), rna(v.y), rna(v.z), rna(v.w));
        ((float4*)g_x)[i] = o;
    } else {
        int j = (b - NB_T1 - NB_T2 - NB_CX)*256 + tid;
        if (j < E_NUM) g_cnt[j] = 0;
        if (j < RCAP)  g_list[j] = -1;
    }
}

// ---------------- router ----------------
__global__ void router_kernel(const float* __restrict__ x, const float* __restrict__ rw){
    __shared__ float srw[E_NUM*H_DIM];
    __shared__ float red[128];
    int tid = threadIdx.x;
    for (int i = tid; i < E_NUM*H_DIM; i += 128) srw[i] = rw[i];
    __syncthreads();
    int t = blockIdx.x*128 + tid;
    const float* xr = x + (size_t)t*H_DIM;
    float l[E_NUM];
#pragma unroll
    for (int e = 0; e < E_NUM; e++) l[e] = 0.f;
    for (int h = 0; h < H_DIM; h++){
        float xv = xr[h];
#pragma unroll
        for (int e = 0; e < E_NUM; e++) l[e] += xv * srw[e*H_DIM + h];
    }
    int i0 = 0;
#pragma unroll
    for (int e = 1; e < E_NUM; e++) if (l[e] > l[i0]) i0 = e;
    int i1 = (i0 == 0) ? 1 : 0;
#pragma unroll
    for (int e = 0; e < E_NUM; e++) if (e != i0 && l[e] > l[i1]) i1 = e;
    float m2 = fmaxf(l[i0], l[i1]);
    float e0 = expf(l[i0]-m2), e1 = expf(l[i1]-m2);
    float inv = 1.f/(e0+e1);
    int p0 = atomicAdd(&g_cnt[i0],1);
    int p1 = atomicAdd(&g_cnt[i1],1);
    g_eidx[2*t]=i0; g_eidx[2*t+1]=i1;
    g_pos[2*t]=p0;  g_pos[2*t+1]=p1;
    g_wgt[2*t]=e0*inv; g_wgt[2*t+1]=e1*inv;

    float m8 = l[i0], p[E_NUM], s8 = 0.f;
#pragma unroll
    for (int e = 0; e < E_NUM; e++){ p[e] = expf(l[e]-m8); s8 += p[e]; }
    float is8 = 1.f/s8;
    for (int e = 0; e < E_NUM; e++){
        red[tid] = p[e]*is8;
        __syncthreads();
        for (int s = 64; s > 0; s >>= 1){ if (tid < s) red[tid] += red[tid+s]; __syncthreads(); }
        if (tid == 0) g_partsP[blockIdx.x][e] = red[0];
        __syncthreads();
    }
}

// ---------------- scatter ----------------
__global__ void scatter_kernel(){
    int i = blockIdx.x*blockDim.x + threadIdx.x;
    if (i < NROWS){
        int e = g_eidx[i];
        int base = 0;
#pragma unroll
        for (int q = 0; q < E_NUM; q++){
            int pad = ((g_cnt[q] + 127) >> 7) << 7;
            if (q < e) base += pad;
        }
        g_list[base + g_pos[i]] = i;
    }
}

// ---------------- GEMM1 (tf32 1-pass): gate+up + SwiGLU epilogue ----------------
__global__ __launch_bounds__(256,2) void gemm1_mma(){
    int f0 = blockIdx.x * 64;
    int tid = threadIdx.x;

    int e, m0, base;
    if (!tile_scan(blockIdx.y, e, m0, base)) return;

    extern __shared__ char dsm[];
    __shared__ int stok[BM];

    if (tid < BM){
        int li = g_list[base + m0 + tid];
        stok[tid] = (li < 0) ? -1 : (li >> 1);
    }
    __syncthreads();

    uint32_t sb = s2u(dsm);

    // loader: thread -> (row = tid>>1, 64B half h2)
    int lrow = tid >> 1;
    int h2 = tid & 1;
    uint32_t dA = (uint32_t)lrow*144 + h2*64;
    uint32_t dB = SUBA + dA;
    int tok = stok[lrow];
    int anb = (tok < 0) ? 0 : 16;
    const char* asrc = (const char*)g_x + ((size_t)(tok < 0 ? 0 : tok))*4096 + h2*64;
    int nrow = (lrow < 64) ? (f0 + lrow) : (F_DIM + f0 + (lrow - 64));
    const char* bsrc = (const char*)g_b1 + ((size_t)e*N1 + nrow)*4096 + h2*64;

    // warps: 4m x 2n (warp tile 32m x [gate32|up32])
    int wid = tid >> 5, lane = tid & 31;
    int wm = wid & 3, wn = wid >> 2;
    int g = lane >> 2, tg = lane & 3;

    uint32_t aAddr[2];
#pragma unroll
    for (int mt = 0; mt < 2; mt++) aAddr[mt] = (uint32_t)((wm*32 + mt*16 + g)*144 + tg*4);
    uint32_t bAddr[8];
#pragma unroll
    for (int j = 0; j < 4; j++){
        bAddr[j]   = SUBA + (uint32_t)((wn*32 + j*8 + g)*144 + tg*4);        // gate
        bAddr[4+j] = SUBA + (uint32_t)((64 + wn*32 + j*8 + g)*144 + tg*4);   // up
    }

    float accG[2][4][4], accU[2][4][4];
#pragma unroll
    for (int mt = 0; mt < 2; mt++)
#pragma unroll
        for (int j = 0; j < 4; j++)
#pragma unroll
            for (int p = 0; p < 4; p++){ accG[mt][j][p] = 0.f; accU[mt][j][p] = 0.f; }

    // prefetch k=0
#pragma unroll
    for (int i = 0; i < 4; i++){
        cp16(sb + dA + i*16, asrc + i*16, anb);
        cp16(sb + dB + i*16, bsrc + i*16, 16);
    }
    cp_commit();

    for (int k = 0; k < NK1; k++){
        asm volatile("cp.async.wait_group 0;" ::: "memory");
        __syncthreads();
        if (k + 1 < NK1){
            uint32_t stb2 = sb + ((k+1)&1)*STAGE;
            uint32_t ko = (uint32_t)(k+1)*128;
#pragma unroll
            for (int i = 0; i < 4; i++){
                cp16(stb2 + dA + i*16, asrc + ko + i*16, anb);
                cp16(stb2 + dB + i*16, bsrc + ko + i*16, 16);
            }
            cp_commit();
        }

        uint32_t stb = sb + (k&1)*STAGE;
#pragma unroll
        for (int s = 0; s < 4; s++){
            uint32_t so = (uint32_t)s*32;
            uint32_t a[2][4];
#pragma unroll
            for (int mt = 0; mt < 2; mt++){
                uint32_t ab = stb + aAddr[mt] + so;
                a[mt][0] = lds32(ab);
                a[mt][1] = lds32(ab + 1152);
                a[mt][2] = lds32(ab + 16);
                a[mt][3] = lds32(ab + 1152 + 16);
            }
            uint32_t bg[8][2];
#pragma unroll
            for (int j = 0; j < 8; j++){
                uint32_t bb = stb + bAddr[j] + so;
                bg[j][0] = lds32(bb);
                bg[j][1] = lds32(bb + 16);
            }
#pragma unroll
            for (int mt = 0; mt < 2; mt++)
#pragma unroll
                for (int j = 0; j < 4; j++){
                    mmaT(accG[mt][j], a[mt], bg[j][0],   bg[j][1]);
                    mmaT(accU[mt][j], a[mt], bg[4+j][0], bg[4+j][1]);
                }
        }
    }

    // fused SwiGLU epilogue -> tf32-rounded fp32 h
#pragma unroll
    for (int mt = 0; mt < 2; mt++){
        size_t r0 = (size_t)(base + m0 + wm*32 + mt*16 + g);
        size_t r1 = r0 + 8;
#pragma unroll
        for (int j = 0; j < 4; j++){
            int col = f0 + wn*32 + j*8 + tg*2;
            float gv0 = accG[mt][j][0], gv1 = accG[mt][j][1];
            float gv2 = accG[mt][j][2], gv3 = accG[mt][j][3];
            float uv0 = accU[mt][j][0], uv1 = accU[mt][j][1];
            float uv2 = accU[mt][j][2], uv3 = accU[mt][j][3];
            float h0 = gv0/(1.f+__expf(-gv0))*uv0;
            float h1 = gv1/(1.f+__expf(-gv1))*uv1;
            float h2v = gv2/(1.f+__expf(-gv2))*uv2;
            float h3 = gv3/(1.f+__expf(-gv3))*uv3;
            *(float2*)&g_h[r0*F_DIM + col] = make_float2(rna(h0), rna(h1));
            *(float2*)&g_h[r1*F_DIM + col] = make_float2(rna(h2v), rna(h3));
        }
    }
}

// ---------------- GEMM2 (tf32 1-pass): y = (h @ WdT) * w ----------------
__global__ __launch_bounds__(256,2) void gemm2_mma(){
    int n0 = blockIdx.x * 128;
    int tid = threadIdx.x;

    int e, m0, base;
    if (!tile_scan(blockIdx.y, e, m0, base)) return;

    extern __shared__ char dsm[];
    __shared__ int   sli[BM];
    __shared__ float swt[BM];

    if (tid < BM){
        int li = g_list[base + m0 + tid];
        sli[tid] = li;
        swt[tid] = (li < 0) ? 0.f : g_wgt[li];
    }
    __syncthreads();

    uint32_t sb = s2u(dsm);

    int lrow = tid >> 1;
    int h2 = tid & 1;
    uint32_t dA = (uint32_t)lrow*144 + h2*64;
    uint32_t dB = SUBA + dA;
    const char* asrc = (const char*)g_h + (size_t)(base + m0 + lrow)*(F_DIM*4) + h2*64;
    const char* bsrc = (const char*)g_b2 + ((size_t)e*H_DIM + n0 + lrow)*(F_DIM*4) + h2*64;

    int wid = tid >> 5, lane = tid & 31;
    int wm = wid & 3, wn = wid >> 2;
    int g = lane >> 2, tg = lane & 3;

    uint32_t aAddr[2];
#pragma unroll
    for (int mt = 0; mt < 2; mt++) aAddr[mt] = (uint32_t)((wm*32 + mt*16 + g)*144 + tg*4);
    uint32_t bAddr[8];
#pragma unroll
    for (int j = 0; j < 8; j++) bAddr[j] = SUBA + (uint32_t)((wn*64 + j*8 + g)*144 + tg*4);

    float acc[2][8][4];
#pragma unroll
    for (int mt = 0; mt < 2; mt++)
#pragma unroll
        for (int j = 0; j < 8; j++)
#pragma unroll
            for (int p = 0; p < 4; p++) acc[mt][j][p] = 0.f;

#pragma unroll
    for (int i = 0; i < 4; i++){
        cp16(sb + dA + i*16, asrc + i*16, 16);
        cp16(sb + dB + i*16, bsrc + i*16, 16);
    }
    cp_commit();

    for (int k = 0; k < NK2; k++){
        asm volatile("cp.async.wait_group 0;" ::: "memory");
        __syncthreads();
        if (k + 1 < NK2){
            uint32_t stb2 = sb + ((k+1)&1)*STAGE;
            uint32_t ko = (uint32_t)(k+1)*128;
#pragma unroll
            for (int i = 0; i < 4; i++){
                cp16(stb2 + dA + i*16, asrc + ko + i*16, 16);
                cp16(stb2 + dB + i*16, bsrc + ko + i*16, 16);
            }
            cp_commit();
        }

        uint32_t stb = sb + (k&1)*STAGE;
#pragma unroll
        for (int s = 0; s < 4; s++){
            uint32_t so = (uint32_t)s*32;
            uint32_t a[2][4];
#pragma unroll
            for (int mt = 0; mt < 2; mt++){
                uint32_t ab = stb + aAddr[mt] + so;
                a[mt][0] = lds32(ab);
                a[mt][1] = lds32(ab + 1152);
                a[mt][2] = lds32(ab + 16);
                a[mt][3] = lds32(ab + 1152 + 16);
            }
            uint32_t bg[8][2];
#pragma unroll
            for (int j = 0; j < 8; j++){
                uint32_t bb = stb + bAddr[j] + so;
                bg[j][0] = lds32(bb);
                bg[j][1] = lds32(bb + 16);
            }
#pragma unroll
            for (int mt = 0; mt < 2; mt++)
#pragma unroll
                for (int j = 0; j < 8; j++)
                    mmaT(acc[mt][j], a[mt], bg[j][0], bg[j][1]);
        }
    }

    // scaled epilogue -> g_y
#pragma unroll
    for (int mt = 0; mt < 2; mt++){
        int rl0 = wm*32 + mt*16 + g;
        int rl1 = rl0 + 8;
        int li0 = sli[rl0], li1 = sli[rl1];
        float w0 = swt[rl0], w1 = swt[rl1];
#pragma unroll
        for (int j = 0; j < 8; j++){
            int col = n0 + wn*64 + j*8 + tg*2;
            if (li0 >= 0){
                float2 v = make_float2(acc[mt][j][0]*w0, acc[mt][j][1]*w0);
                *(float2*)&g_y[(size_t)li0*H_DIM + col] = v;
            }
            if (li1 >= 0){
                float2 v = make_float2(acc[mt][j][2]*w1, acc[mt][j][3]*w1);
                *(float2*)&g_y[(size_t)li1*H_DIM + col] = v;
            }
        }
    }
}

// ---------------- combine + aux ----------------
__global__ void combine_kernel(float* __restrict__ out){
    long long gid = (long long)blockIdx.x*256 + threadIdx.x;
    if (gid >= (long long)T_TOK*H_DIM/4) return;
    int t = (int)(gid >> 8);
    int c = (int)(gid & 255) * 4;
    float4 a = *(const float4*)&g_y[(size_t)(2*t)*H_DIM + c];
    float4 b = *(const float4*)&g_y[(size_t)(2*t+1)*H_DIM + c];
    *(float4*)&out[(size_t)t*H_DIM + c] = make_float4(a.x+b.x, a.y+b.y, a.z+b.z, a.w+b.w);
}
__global__ void aux_kernel(float* __restrict__ out){
    if (threadIdx.x == 0){
        float aux = 0.f;
        for (int e = 0; e < E_NUM; e++){
            float P = 0.f;
            for (int b = 0; b < NBLK_ROUTER; b++) P += g_partsP[b][e];
            P *= (1.f/(float)T_TOK);
            float f = (float)g_cnt[e] / (float)NROWS;
            aux += f*P;
        }
        out[(size_t)T_TOK*H_DIM] = (float)E_NUM * aux;
    }
}

// ---------------- launch ----------------
extern "C" void kernel_launch(void* const* d_in, const int* in_sizes, int n_in,
                              void* d_out, int out_size){
    const float* x  = (const float*)d_in[0];
    const float* rw = (const float*)d_in[1];
    const float* wg = (const float*)d_in[2];
    const float* wu = (const float*)d_in[3];
    const float* wd = (const float*)d_in[4];
    float* out = (float*)d_out;

    cudaFuncSetAttribute(gemm1_mma, cudaFuncAttributeMaxDynamicSharedMemorySize, SMEM_DYN);
    cudaFuncSetAttribute(gemm2_mma, cudaFuncAttributeMaxDynamicSharedMemorySize, SMEM_DYN);

    prep_kernel<<<NB_T1 + NB_T2 + NB_CX + NB_IN, 256>>>(x, wg, wu, wd);
    router_kernel<<<NBLK_ROUTER, 128>>>(x, rw);
    scatter_kernel<<<(NROWS+255)/256, 256>>>();

    gemm1_mma<<<dim3(F_DIM/64, MAXTILES), 256, SMEM_DYN>>>();
    gemm2_mma<<<dim3(H_DIM/128, MAXTILES), 256, SMEM_DYN>>>();

    combine_kernel<<<(int)(((long long)T_TOK*H_DIM/4 + 255)/256), 256>>>(out);
    if (out_size > T_TOK*H_DIM) aux_kernel<<<1, 32>>>(out);
}